// round 16
// baseline (speedup 1.0000x reference)
#include <cuda_runtime.h>

#define N 131072
#define D 128
#define K 1024
#define NITERS 10
#define CHUNK 512
#define CHUNKS (N / CHUNK)   /* 256 */

// ---------------- persistent device scratch (no allocations allowed) ----------------
__device__ float g_centroids[K * D];
__device__ float g_csq[K];
__device__ float g_xsq[N];
__device__ int   g_assign[N];
__device__ int   g_rank[N];
__device__ int   g_order[N];
__device__ int   g_hist[CHUNKS * K];
__device__ int   g_counts_i[K];
__device__ int   g_offs[K];

// ---------------- assignment kernel: argmin_k ||x - c_k||^2 ----------------
// 512 threads, 2 CTAs/SM (8 warps/SMSP). tx = tid&15, ty = tid>>4.
// Per-thread micro-tile: 4 CONTIGUOUS points x 8 cents (2 QUADS at tx*4 and
// tx*4+64). a: one LDS.128 (4 points); b: two LDS.128 (cent quads).
// Scalar chains per (point,cent): ascending-d fma.rn.f32x2, lanes = cent parity
// (FROZEN numerics — identical chains to the golden-matching kernels).
#define XST_PITCH 132
#define XST_FLOATS (128 * XST_PITCH)          /* [128 d][132 pts] = 67584 B */
#define CTH_PITCH 132                          /* 16B-aligned rows for LDS.128 */
#define CTH_FLOATS (64 * CTH_PITCH)           /* [64 d][132 c] = 33792 B */
#define SMEM_FLOATS (XST_FLOATS + CTH_FLOATS)
#define SMEM_BYTES (SMEM_FLOATS * 4)          /* 101376 B -> 2 CTAs/SM */

__global__ __launch_bounds__(512, 2)
void assign_kernel(const float* __restrict__ x) {
    extern __shared__ float sm[];
    float* XsT = sm;                       // [128 d][XST_PITCH pts]
    float* CtH = sm + XST_FLOATS;          // [64 d][CTH_PITCH c]

    const int tid = threadIdx.x;
    const int tx = tid & 15;
    const int ty = tid >> 4;               // 0..31
    const int pBase = blockIdx.x * 128;

    // Load X tile TRANSPOSED: XsT[d][p] (coalesced float4 global reads).
    #pragma unroll
    for (int s = 0; s < 8; s++) {
        const int idx = tid + s * 512;
        const int p = idx >> 5;            // 0..127
        const int g = idx & 31;            // d-group of 4
        float4 v = *(const float4*)(x + (size_t)(pBase + p) * D + g * 4);
        XsT[(g * 4 + 0) * XST_PITCH + p] = v.x;
        XsT[(g * 4 + 1) * XST_PITCH + p] = v.y;
        XsT[(g * 4 + 2) * XST_PITCH + p] = v.z;
        XsT[(g * 4 + 3) * XST_PITCH + p] = v.w;
    }

    // Points: p = ty*4 + ii, ii in [0,4)
    float xs[4];
    float bestv[4];
    int   besti[4];
    #pragma unroll
    for (int ii = 0; ii < 4; ii++) {
        xs[ii] = g_xsq[pBase + ty * 4 + ii];
        bestv[ii] = 3.4e38f;
        besti[ii] = 0;
    }

    for (int chunk = 0; chunk < 8; chunk++) {
        const int c0 = chunk * 128;

        unsigned long long acc[4][4];      // [point ii][cent pair q]
        #pragma unroll
        for (int ii = 0; ii < 4; ii++)
            #pragma unroll
            for (int q = 0; q < 4; q++) acc[ii][q] = 0ull;

        #pragma unroll
        for (int half = 0; half < 2; half++) {
            const int h0 = half * 64;
            __syncthreads();  // protect CtH before overwrite
            // Load centroid half-chunk TRANSPOSED: CtH[d][cent], d in [h0,h0+64)
            {
                const int w = tid >> 5, lane = tid & 31;   // w 0..15
                const int cl = lane >> 4;                  // 0..1
                const int d4 = lane & 15;                  // float4 group along d
                #pragma unroll
                for (int s = 0; s < 4; s++) {
                    const int c = (w * 2 + cl) + s * 32;   // 0..127
                    float4 v = *(const float4*)(g_centroids +
                                 (size_t)(c0 + c) * D + h0 + d4 * 4);
                    CtH[(d4 * 4 + 0) * CTH_PITCH + c] = v.x;
                    CtH[(d4 * 4 + 1) * CTH_PITCH + c] = v.y;
                    CtH[(d4 * 4 + 2) * CTH_PITCH + c] = v.z;
                    CtH[(d4 * 4 + 3) * CTH_PITCH + c] = v.w;
                }
            }
            __syncthreads();

            #pragma unroll 4
            for (int d = 0; d < 64; d++) {
                const int dd = h0 + d;
                // b: 2 LDS.128 = cent quads at tx*4 and tx*4+64
                const ulonglong2 bq0 = *(const ulonglong2*)
                    (CtH + d * CTH_PITCH + tx * 4);
                const ulonglong2 bq1 = *(const ulonglong2*)
                    (CtH + d * CTH_PITCH + 64 + tx * 4);
                unsigned long long b2[4];
                b2[0] = bq0.x; b2[1] = bq0.y; b2[2] = bq1.x; b2[3] = bq1.y;
                // a: one LDS.128 = 4 contiguous points at dim dd
                const float4 av = *(const float4*)(XsT + dd * XST_PITCH + ty * 4);
                #pragma unroll
                for (int ii = 0; ii < 4; ii++) {
                    const float a = (ii == 0) ? av.x : (ii == 1) ? av.y
                                  : (ii == 2) ? av.z : av.w;
                    unsigned long long a2;
                    asm("mov.b64 %0, {%1, %1};" : "=l"(a2) : "f"(a));
                    #pragma unroll
                    for (int q = 0; q < 4; q++)
                        asm("fma.rn.f32x2 %0, %1, %2, %0;"
                            : "+l"(acc[ii][q]) : "l"(a2), "l"(b2[q]));
                }
            }
        }

        // Epilogue: d = xsq - 2*dot + csq ; running argmin.
        // Pair q covers cents c0 + (q>>1)*64 + tx*4 + (q&1)*2 + {0,1};
        // q ascending => cent indices ascending per thread (first-wins ties).
        float cs0[4], cs1[4];
        int   cb[4];
        #pragma unroll
        for (int q = 0; q < 4; q++) {
            const int c = c0 + (q >> 1) * 64 + tx * 4 + (q & 1) * 2;
            cb[q] = c;
            cs0[q] = g_csq[c];
            cs1[q] = g_csq[c + 1];
        }
        #pragma unroll
        for (int ii = 0; ii < 4; ii++) {
            #pragma unroll
            for (int q = 0; q < 4; q++) {
                float v0, v1;
                asm("mov.b64 {%0, %1}, %2;" : "=f"(v0), "=f"(v1) : "l"(acc[ii][q]));
                const float d0 = fmaf(-2.f, v0, xs[ii]) + cs0[q];
                const float d1 = fmaf(-2.f, v1, xs[ii]) + cs1[q];
                if (d0 < bestv[ii]) { bestv[ii] = d0; besti[ii] = cb[q]; }
                if (d1 < bestv[ii]) { bestv[ii] = d1; besti[ii] = cb[q] + 1; }
            }
        }
    }

    // Cross-thread argmin reduction over the 16 tx lanes per point (lex order).
    __syncthreads();
    float* rv = sm;                         // [128][16] floats
    int*   ri = (int*)(sm + 128 * 16);      // [128][16] ints
    #pragma unroll
    for (int ii = 0; ii < 4; ii++) {
        const int p = ty * 4 + ii;
        rv[p * 16 + tx] = bestv[ii];
        ri[p * 16 + tx] = besti[ii];
    }
    __syncthreads();
    if (tid < 128) {
        float bv = rv[tid * 16];
        int   bi = ri[tid * 16];
        #pragma unroll
        for (int t = 1; t < 16; t++) {
            const float v = rv[tid * 16 + t];
            const int  ix = ri[tid * 16 + t];
            if (v < bv || (v == bv && ix < bi)) { bv = v; bi = ix; }
        }
        g_assign[pBase + tid] = bi;
    }
}

// ---------------- deterministic stable counting-sort of points by cluster ----------------
__global__ __launch_bounds__(256)
void rank_kernel() {
    __shared__ int hist[8][K];
    const int warp = threadIdx.x >> 5;
    const int lane = threadIdx.x & 31;
    const int chunk = blockIdx.x * 8 + warp;
    int* h = hist[warp];
    for (int i = lane; i < K; i += 32) h[i] = 0;
    __syncwarp();
    const int base_n = chunk * CHUNK;
    for (int g = 0; g < CHUNK / 32; g++) {
        const int n = base_n + g * 32 + lane;
        const int a = g_assign[n];
        const unsigned mask = __match_any_sync(0xffffffffu, a);
        const int before = __popc(mask & ((1u << lane) - 1u));
        const int b = h[a];
        __syncwarp();
        g_rank[n] = b + before;
        if (lane == (int)(__ffs(mask) - 1)) h[a] = b + __popc(mask);
        __syncwarp();
    }
    for (int i = lane; i < K; i += 32) g_hist[chunk * K + i] = h[i];
}

// Fused: per-cluster exclusive prefix over chunks + counts + cluster offsets.
// Single block of K=1024 threads (integer arithmetic, fully deterministic).
__global__ __launch_bounds__(1024)
void scan_kernel() {
    __shared__ int s[K];
    const int k = threadIdx.x;
    int run = 0;
    #pragma unroll 8
    for (int c = 0; c < CHUNKS; c++) {
        const int t = g_hist[c * K + k];
        g_hist[c * K + k] = run;
        run += t;
    }
    g_counts_i[k] = run;
    s[k] = run;
    __syncthreads();
    const int my = run;
    for (int o = 1; o < K; o <<= 1) {
        const int t = (k >= o) ? s[k - o] : 0;
        __syncthreads();
        s[k] += t;
        __syncthreads();
    }
    g_offs[k] = s[k] - my;
}

__global__ void scatter_kernel() {
    const int n = blockIdx.x * blockDim.x + threadIdx.x;
    if (n >= N) return;
    const int a = g_assign[n];
    const int chunk = n / CHUNK;
    const int slot = g_offs[a] + g_hist[chunk * K + a] + g_rank[n];
    g_order[slot] = n;
}

// Update + csq fused. Update: fp32 serial fold, ADJACENT-PAIR-SWAPPED ascending
// order (FROZEN — matched golden), plain fp32 divide (0/0 -> NaN). csq: serial
// fmaf chain over the freshly rounded fp32 centroid (FROZEN form), by thread 0.
__global__ __launch_bounds__(128)
void update_kernel(const float* __restrict__ x) {
    __shared__ float cent[128];
    const int k = blockIdx.x;
    const int d = threadIdx.x;
    const int cnt = g_counts_i[k];
    const int off = g_offs[k];
    float s = 0.f;
    for (int j = 0; j < cnt; j++) {
        int jj = j ^ 1;
        if (jj >= cnt) jj = j;          // odd tail element stays in place
        const int n = g_order[off + jj];
        s += x[(size_t)n * D + d];
    }
    const float c = s / (float)cnt;
    g_centroids[k * D + d] = c;
    cent[d] = c;
    __syncthreads();
    if (d == 0) {
        float q = 0.f;
        #pragma unroll 8
        for (int dd = 0; dd < D; dd++) q = fmaf(cent[dd], cent[dd], q);
        g_csq[k] = q;
    }
}

// ---------------- support kernels ----------------
__global__ void init_centroids_kernel(const float* __restrict__ x) {
    const int i = blockIdx.x * blockDim.x + threadIdx.x;
    if (i < K * D) g_centroids[i] = x[i];  // c0 = x[:K]
}

__global__ void xsq_kernel(const float* __restrict__ x) {
    const int gtid = blockIdx.x * blockDim.x + threadIdx.x;
    const int w = gtid >> 5;
    const int lane = gtid & 31;
    if (w < N) {
        float4 v = *(const float4*)(x + (size_t)w * D + lane * 4);
        float s = v.x * v.x + v.y * v.y + v.z * v.z + v.w * v.w;
        #pragma unroll
        for (int o = 16; o; o >>= 1) s += __shfl_down_sync(0xffffffffu, s, o);
        if (lane == 0) g_xsq[w] = s;
    }
}

// csq (initial centroids only): serial fma chain (FROZEN form).
__global__ void csq_kernel() {
    const int k = blockIdx.x * blockDim.x + threadIdx.x;
    if (k < K) {
        const float* c = g_centroids + (size_t)k * D;
        float s = 0.f;
        #pragma unroll 8
        for (int d = 0; d < D; d++) s = fmaf(c[d], c[d], s);
        g_csq[k] = s;
    }
}

// Output (float32): [clusters(131072), centroids(131072), counts(1024)]
__global__ void writeout_kernel(float* __restrict__ out, int out_size) {
    const int i = blockIdx.x * blockDim.x + threadIdx.x;
    if (i >= out_size) return;
    if (i < N) {
        out[i] = (float)g_assign[i];
    } else if (i < N + K * D) {
        out[i] = g_centroids[i - N];
    } else if (i < N + K * D + K) {
        out[i] = (float)g_counts_i[i - N - K * D];
    }
}

// ---------------- launch ----------------
extern "C" void kernel_launch(void* const* d_in, const int* in_sizes, int n_in,
                              void* d_out, int out_size) {
    const float* x = (const float*)d_in[0];
    float* out = (float*)d_out;

    cudaFuncSetAttribute(assign_kernel,
                         cudaFuncAttributeMaxDynamicSharedMemorySize, SMEM_BYTES);

    init_centroids_kernel<<<(K * D + 255) / 256, 256>>>(x);
    xsq_kernel<<<(N * 32 + 255) / 256, 256>>>(x);
    csq_kernel<<<(K + 255) / 256, 256>>>();

    for (int it = 0; it < NITERS; it++) {
        assign_kernel<<<N / 128, 512, SMEM_BYTES>>>(x);
        rank_kernel<<<CHUNKS / 8, 256>>>();
        scan_kernel<<<1, 1024>>>();
        scatter_kernel<<<(N + 255) / 256, 256>>>();
        update_kernel<<<K, 128>>>(x);
    }
    writeout_kernel<<<(out_size + 255) / 256, 256>>>(out, out_size);
}

// round 17
// speedup vs baseline: 1.0942x; 1.0942x over previous
#include <cuda_runtime.h>

#define N 131072
#define D 128
#define K 1024
#define NITERS 10
#define CHUNK 512
#define CHUNKS (N / CHUNK)   /* 256 */

#define EPS 1.0f
#define CAP 32

// ---------------- persistent device scratch (no allocations allowed) ----------------
__device__ float g_centroids[K * D];
__device__ float g_csq[K];
__device__ float g_xsq[N];
__device__ int   g_assign[N];
__device__ int   g_rank[N];
__device__ int   g_order[N];
__device__ int   g_hist[CHUNKS * K];
__device__ int   g_counts_i[K];
__device__ int   g_offs[K];

// ---------------- assignment: tf32 tensor screening + exact fp32 re-eval ----------------
// Block 256 thr (8 warps), 1 CTA/SM, grid 1024 (128 points per block).
// Phase 1: approx distances via mma.sync.m16n8k8.tf32 (tensor pipe).
//   Guaranteed error bound |approx-exact| <= 2*sqrt(xsq*csq)*2^-11 ~ 0.2 << EPS.
// Phase 2: per point, candidates = {c : approx_d <= approx_min + EPS} (always
//   contains the exact lex-min). Exact re-eval with the FROZEN chain:
//   dot = ascending-d fma.rn scalar chain; dist = fmaf(-2,dot,xsq)+csq;
//   lex (value, index) min -> bit-identical to the golden-matching kernel.
// Smem: Xs_tf32[128][132], Cs_tf32[128][132], pmin[128], pcnt[128], candc[128][CAP]
#define XP 132
#define SM_XS 0
#define SM_CS (128 * XP)                       /* u32 offsets */
#define SM_PMIN (SM_CS + 128 * XP)
#define SM_PCNT (SM_PMIN + 128)
#define SM_CAND (SM_PCNT + 128)
#define SM_WORDS (SM_CAND + 128 * CAP)
#define SMEM_BYTES_TC (SM_WORDS * 4)           /* 152576 B */

__device__ __forceinline__ unsigned f2tf32(float f) {
    unsigned u;
    asm("cvt.rna.tf32.f32 %0, %1;" : "=r"(u) : "f"(f));
    return u;
}

__global__ __launch_bounds__(256, 1)
void assign_tc_kernel(const float* __restrict__ x) {
    extern __shared__ unsigned smw[];
    unsigned* Xs = smw + SM_XS;                // [128 pts][XP] tf32
    unsigned* Cs = smw + SM_CS;                // [128 cents][XP] tf32
    float*    pmin = (float*)(smw + SM_PMIN);  // [128]
    int*      pcnt = (int*)(smw + SM_PCNT);    // [128]
    int*      candc = (int*)(smw + SM_CAND);   // [128][CAP]

    const int tid = threadIdx.x;
    const int wid = tid >> 5;
    const int lane = tid & 31;
    const int gid = lane >> 2;                 // 0..7
    const int tq = lane & 3;                   // 0..3
    const int p0 = wid * 16;                   // warp's 16 point rows
    const int pBase = blockIdx.x * 128;

    // Load X tile, convert to tf32: Xs[p][k]
    #pragma unroll
    for (int s = 0; s < 16; s++) {
        const int idx = tid + s * 256;
        const int p = idx >> 5;                // 0..127
        const int g = idx & 31;                // float4 group along k
        float4 v = *(const float4*)(x + (size_t)(pBase + p) * D + g * 4);
        Xs[p * XP + g * 4 + 0] = f2tf32(v.x);
        Xs[p * XP + g * 4 + 1] = f2tf32(v.y);
        Xs[p * XP + g * 4 + 2] = f2tf32(v.z);
        Xs[p * XP + g * 4 + 3] = f2tf32(v.w);
    }
    if (tid < 128) { pmin[tid] = 3.4e38f; pcnt[tid] = 0; }

    const float xs_lo = g_xsq[pBase + p0 + gid];
    const float xs_hi = g_xsq[pBase + p0 + gid + 8];

    for (int chunk = 0; chunk < 8; chunk++) {
        const int cbase = chunk * 128;
        __syncthreads();
        // Load centroid chunk, tf32: Cs[c][k]
        #pragma unroll
        for (int s = 0; s < 16; s++) {
            const int idx = tid + s * 256;
            const int c = idx >> 5;
            const int g = idx & 31;
            float4 v = *(const float4*)(g_centroids + (size_t)(cbase + c) * D + g * 4);
            Cs[c * XP + g * 4 + 0] = f2tf32(v.x);
            Cs[c * XP + g * 4 + 1] = f2tf32(v.y);
            Cs[c * XP + g * 4 + 2] = f2tf32(v.z);
            Cs[c * XP + g * 4 + 3] = f2tf32(v.w);
        }
        __syncthreads();

        float dl[32], dh[32];   // per-lane dists: [nt][parity] for row lo / hi
        #pragma unroll
        for (int nt = 0; nt < 16; nt++) {
            float c0 = 0.f, c1 = 0.f, c2 = 0.f, c3 = 0.f;
            const unsigned* xa = Xs + (p0 + gid) * XP + tq;
            const unsigned* xb = Xs + (p0 + gid + 8) * XP + tq;
            const unsigned* cc = Cs + (nt * 8 + gid) * XP + tq;
            #pragma unroll 4
            for (int ks = 0; ks < 16; ks++) {
                const int k = ks * 8;
                const unsigned a0 = xa[k],     a1 = xb[k];
                const unsigned a2 = xa[k + 4], a3 = xb[k + 4];
                const unsigned b0 = cc[k],     b1 = cc[k + 4];
                asm volatile(
                    "mma.sync.aligned.m16n8k8.row.col.f32.tf32.tf32.f32 "
                    "{%0,%1,%2,%3}, {%4,%5,%6,%7}, {%8,%9}, {%0,%1,%2,%3};"
                    : "+f"(c0), "+f"(c1), "+f"(c2), "+f"(c3)
                    : "r"(a0), "r"(a1), "r"(a2), "r"(a3), "r"(b0), "r"(b1));
            }
            const int cA = cbase + nt * 8 + tq * 2;
            const float csA = g_csq[cA];
            const float csB = g_csq[cA + 1];
            dl[nt * 2 + 0] = fmaf(-2.f, c0, xs_lo) + csA;
            dl[nt * 2 + 1] = fmaf(-2.f, c1, xs_lo) + csB;
            dh[nt * 2 + 0] = fmaf(-2.f, c2, xs_hi) + csA;
            dh[nt * 2 + 1] = fmaf(-2.f, c3, xs_hi) + csB;
        }

        // chunk-min per row (cross 4 lanes of the quad), update per-point min
        float ml = 3.4e38f, mh = 3.4e38f;
        #pragma unroll
        for (int i = 0; i < 32; i++) { ml = fminf(ml, dl[i]); mh = fminf(mh, dh[i]); }
        #pragma unroll
        for (int o = 1; o <= 2; o <<= 1) {
            ml = fminf(ml, __shfl_xor_sync(0xffffffffu, ml, o));
            mh = fminf(mh, __shfl_xor_sync(0xffffffffu, mh, o));
        }
        if (tq == 0) {
            pmin[p0 + gid]     = fminf(pmin[p0 + gid], ml);
            pmin[p0 + gid + 8] = fminf(pmin[p0 + gid + 8], mh);
        }
        __syncwarp();
        const float thr_lo = pmin[p0 + gid] + EPS;
        const float thr_hi = pmin[p0 + gid + 8] + EPS;
        #pragma unroll
        for (int nt = 0; nt < 16; nt++) {
            #pragma unroll
            for (int j = 0; j < 2; j++) {
                const int c = cbase + nt * 8 + tq * 2 + j;
                if (dl[nt * 2 + j] <= thr_lo) {
                    const int s = atomicAdd(&pcnt[p0 + gid], 1);
                    if (s < CAP) candc[(p0 + gid) * CAP + s] = c;
                }
                if (dh[nt * 2 + j] <= thr_hi) {
                    const int s = atomicAdd(&pcnt[p0 + gid + 8], 1);
                    if (s < CAP) candc[(p0 + gid + 8) * CAP + s] = c;
                }
            }
        }
    }

    // Exact pass: frozen fp32 chain on candidates, lex (value, index) min.
    __syncthreads();
    if (tid < 128) {
        const int p = pBase + tid;
        const float xsv = g_xsq[p];
        const float4* xr = (const float4*)(x + (size_t)p * D);
        float4 xv[32];
        #pragma unroll 8
        for (int g = 0; g < 32; g++) xv[g] = xr[g];

        float bv = 3.4e38f;
        int   bi = 0;
        const int cnt = pcnt[tid];
        const int m = (cnt > CAP) ? K : cnt;   // overflow -> exact scan of all
        for (int s = 0; s < m; s++) {
            const int c = (cnt > CAP) ? s : candc[tid * CAP + s];
            const float4* cr = (const float4*)(g_centroids + (size_t)c * D);
            float dot = 0.f;
            #pragma unroll 8
            for (int g = 0; g < 32; g++) {
                const float4 cv = cr[g];
                dot = fmaf(xv[g].x, cv.x, dot);
                dot = fmaf(xv[g].y, cv.y, dot);
                dot = fmaf(xv[g].z, cv.z, dot);
                dot = fmaf(xv[g].w, cv.w, dot);
            }
            const float dist = fmaf(-2.f, dot, xsv) + g_csq[c];
            if (dist < bv || (dist == bv && c < bi)) { bv = dist; bi = c; }
        }
        g_assign[p] = bi;
    }
}

// ---------------- deterministic stable counting-sort of points by cluster ----------------
__global__ __launch_bounds__(256)
void rank_kernel() {
    __shared__ int hist[8][K];
    const int warp = threadIdx.x >> 5;
    const int lane = threadIdx.x & 31;
    const int chunk = blockIdx.x * 8 + warp;
    int* h = hist[warp];
    for (int i = lane; i < K; i += 32) h[i] = 0;
    __syncwarp();
    const int base_n = chunk * CHUNK;
    for (int g = 0; g < CHUNK / 32; g++) {
        const int n = base_n + g * 32 + lane;
        const int a = g_assign[n];
        const unsigned mask = __match_any_sync(0xffffffffu, a);
        const int before = __popc(mask & ((1u << lane) - 1u));
        const int b = h[a];
        __syncwarp();
        g_rank[n] = b + before;
        if (lane == (int)(__ffs(mask) - 1)) h[a] = b + __popc(mask);
        __syncwarp();
    }
    for (int i = lane; i < K; i += 32) g_hist[chunk * K + i] = h[i];
}

// Fused: per-cluster exclusive prefix over chunks + counts + cluster offsets.
__global__ __launch_bounds__(1024)
void scan_kernel() {
    __shared__ int s[K];
    const int k = threadIdx.x;
    int run = 0;
    #pragma unroll 8
    for (int c = 0; c < CHUNKS; c++) {
        const int t = g_hist[c * K + k];
        g_hist[c * K + k] = run;
        run += t;
    }
    g_counts_i[k] = run;
    s[k] = run;
    __syncthreads();
    const int my = run;
    for (int o = 1; o < K; o <<= 1) {
        const int t = (k >= o) ? s[k - o] : 0;
        __syncthreads();
        s[k] += t;
        __syncthreads();
    }
    g_offs[k] = s[k] - my;
}

__global__ void scatter_kernel() {
    const int n = blockIdx.x * blockDim.x + threadIdx.x;
    if (n >= N) return;
    const int a = g_assign[n];
    const int chunk = n / CHUNK;
    const int slot = g_offs[a] + g_hist[chunk * K + a] + g_rank[n];
    g_order[slot] = n;
}

// Update + csq fused. Update: fp32 serial fold, ADJACENT-PAIR-SWAPPED ascending
// order (FROZEN — matched golden), plain fp32 divide (0/0 -> NaN). csq: serial
// fmaf chain over the freshly rounded fp32 centroid (FROZEN form), by thread 0.
__global__ __launch_bounds__(128)
void update_kernel(const float* __restrict__ x) {
    __shared__ float cent[128];
    const int k = blockIdx.x;
    const int d = threadIdx.x;
    const int cnt = g_counts_i[k];
    const int off = g_offs[k];
    float s = 0.f;
    for (int j = 0; j < cnt; j++) {
        int jj = j ^ 1;
        if (jj >= cnt) jj = j;          // odd tail element stays in place
        const int n = g_order[off + jj];
        s += x[(size_t)n * D + d];
    }
    const float c = s / (float)cnt;
    g_centroids[k * D + d] = c;
    cent[d] = c;
    __syncthreads();
    if (d == 0) {
        float q = 0.f;
        #pragma unroll 8
        for (int dd = 0; dd < D; dd++) q = fmaf(cent[dd], cent[dd], q);
        g_csq[k] = q;
    }
}

// ---------------- support kernels ----------------
__global__ void init_centroids_kernel(const float* __restrict__ x) {
    const int i = blockIdx.x * blockDim.x + threadIdx.x;
    if (i < K * D) g_centroids[i] = x[i];  // c0 = x[:K]
}

__global__ void xsq_kernel(const float* __restrict__ x) {
    const int gtid = blockIdx.x * blockDim.x + threadIdx.x;
    const int w = gtid >> 5;
    const int lane = gtid & 31;
    if (w < N) {
        float4 v = *(const float4*)(x + (size_t)w * D + lane * 4);
        float s = v.x * v.x + v.y * v.y + v.z * v.z + v.w * v.w;
        #pragma unroll
        for (int o = 16; o; o >>= 1) s += __shfl_down_sync(0xffffffffu, s, o);
        if (lane == 0) g_xsq[w] = s;
    }
}

// csq (initial centroids only): serial fma chain (FROZEN form).
__global__ void csq_kernel() {
    const int k = blockIdx.x * blockDim.x + threadIdx.x;
    if (k < K) {
        const float* c = g_centroids + (size_t)k * D;
        float s = 0.f;
        #pragma unroll 8
        for (int d = 0; d < D; d++) s = fmaf(c[d], c[d], s);
        g_csq[k] = s;
    }
}

// Output (float32): [clusters(131072), centroids(131072), counts(1024)]
__global__ void writeout_kernel(float* __restrict__ out, int out_size) {
    const int i = blockIdx.x * blockDim.x + threadIdx.x;
    if (i >= out_size) return;
    if (i < N) {
        out[i] = (float)g_assign[i];
    } else if (i < N + K * D) {
        out[i] = g_centroids[i - N];
    } else if (i < N + K * D + K) {
        out[i] = (float)g_counts_i[i - N - K * D];
    }
}

// ---------------- launch ----------------
extern "C" void kernel_launch(void* const* d_in, const int* in_sizes, int n_in,
                              void* d_out, int out_size) {
    const float* x = (const float*)d_in[0];
    float* out = (float*)d_out;

    cudaFuncSetAttribute(assign_tc_kernel,
                         cudaFuncAttributeMaxDynamicSharedMemorySize, SMEM_BYTES_TC);

    init_centroids_kernel<<<(K * D + 255) / 256, 256>>>(x);
    xsq_kernel<<<(N * 32 + 255) / 256, 256>>>(x);
    csq_kernel<<<(K + 255) / 256, 256>>>();

    for (int it = 0; it < NITERS; it++) {
        assign_tc_kernel<<<N / 128, 256, SMEM_BYTES_TC>>>(x);
        rank_kernel<<<CHUNKS / 8, 256>>>();
        scan_kernel<<<1, 1024>>>();
        scatter_kernel<<<(N + 255) / 256, 256>>>();
        update_kernel<<<K, 128>>>(x);
    }
    writeout_kernel<<<(out_size + 255) / 256, 256>>>(out, out_size);
}